// round 5
// baseline (speedup 1.0000x reference)
#include <cuda_runtime.h>
#include <cuda_bf16.h>
#include <mma.h>
#include <math.h>
#include <stdint.h>

using namespace nvcuda;

// Problem constants
#define D_MODEL   1024
#define NUM_HEADS 16
#define DK        64
#define B_        2
#define S_        2048
#define M_ROWS    (B_ * S_)   // 4096

// ===========================================================================
// Scratch (__device__ globals, allocation-free)
// ===========================================================================
__device__ __align__(128) float g_Q[(size_t)M_ROWS * D_MODEL];
__device__ __align__(128) float g_K[(size_t)M_ROWS * D_MODEL];
__device__ __align__(128) float g_V[(size_t)M_ROWS * D_MODEL];

__device__ __align__(128) __nv_bfloat16 g_xhi[(size_t)M_ROWS * D_MODEL];
__device__ __align__(128) __nv_bfloat16 g_xlo[(size_t)M_ROWS * D_MODEL];
__device__ __align__(128) __nv_bfloat16 g_Whi[4][(size_t)D_MODEL * D_MODEL];
__device__ __align__(128) __nv_bfloat16 g_Wlo[4][(size_t)D_MODEL * D_MODEL];
__device__ __align__(128) __nv_bfloat16 g_Ahi[(size_t)M_ROWS * D_MODEL];
__device__ __align__(128) __nv_bfloat16 g_Alo[(size_t)M_ROWS * D_MODEL];

// head-major bf16 hi/lo Q,K,V
__device__ __align__(128) __nv_bfloat16 g_Qhi[(size_t)M_ROWS * D_MODEL];
__device__ __align__(128) __nv_bfloat16 g_Qlo[(size_t)M_ROWS * D_MODEL];
__device__ __align__(128) __nv_bfloat16 g_Khi[(size_t)M_ROWS * D_MODEL];
__device__ __align__(128) __nv_bfloat16 g_Klo[(size_t)M_ROWS * D_MODEL];
__device__ __align__(128) __nv_bfloat16 g_Vhi[(size_t)M_ROWS * D_MODEL];
__device__ __align__(128) __nv_bfloat16 g_Vlo[(size_t)M_ROWS * D_MODEL];

// ===========================================================================
// helpers
// ===========================================================================
__device__ __forceinline__ uint32_t smem_u32(const void* p) {
    uint32_t a;
    asm("{ .reg .u64 t; cvta.to.shared.u64 t, %1; cvt.u32.u64 %0, t; }"
        : "=r"(a) : "l"(p));
    return a;
}
__device__ __forceinline__ void cp_async16(uint32_t dst, const void* src) {
    uint64_t gsrc = __cvta_generic_to_global(src);
    asm volatile("cp.async.cg.shared.global [%0], [%1], 16;" :: "r"(dst), "l"(gsrc));
}
__device__ __forceinline__ void cp_async_commit() {
    asm volatile("cp.async.commit_group;" ::: "memory");
}
template <int N>
__device__ __forceinline__ void cp_async_wait() {
    asm volatile("cp.async.wait_group %0;" :: "n"(N) : "memory");
}

// ===========================================================================
// fp32 -> (bf16 hi, bf16 lo) split
// ===========================================================================
__global__ __launch_bounds__(256)
void split_fp32(const float* __restrict__ in, __nv_bfloat16* __restrict__ hi,
                __nv_bfloat16* __restrict__ lo, int n4)
{
    int i = blockIdx.x * 256 + threadIdx.x;
    if (i >= n4) return;
    float4 v = ((const float4*)in)[i];
    __nv_bfloat16 h0 = __float2bfloat16_rn(v.x);
    __nv_bfloat16 h1 = __float2bfloat16_rn(v.y);
    __nv_bfloat16 h2 = __float2bfloat16_rn(v.z);
    __nv_bfloat16 h3 = __float2bfloat16_rn(v.w);
    __nv_bfloat16 l0 = __float2bfloat16_rn(v.x - __bfloat162float(h0));
    __nv_bfloat16 l1 = __float2bfloat16_rn(v.y - __bfloat162float(h1));
    __nv_bfloat16 l2 = __float2bfloat16_rn(v.z - __bfloat162float(h2));
    __nv_bfloat16 l3 = __float2bfloat16_rn(v.w - __bfloat162float(h3));
    ((__nv_bfloat162*)hi)[i * 2 + 0] = __nv_bfloat162(h0, h1);
    ((__nv_bfloat162*)hi)[i * 2 + 1] = __nv_bfloat162(h2, h3);
    ((__nv_bfloat162*)lo)[i * 2 + 0] = __nv_bfloat162(l0, l1);
    ((__nv_bfloat162*)lo)[i * 2 + 1] = __nv_bfloat162(l2, l3);
}

// ===========================================================================
// WMMA bf16x3 GEMM (unchanged from R3)
// ===========================================================================
#define BM 128
#define BN 128
#define BK 32
#define PAD_K 40
#define MAT_BYTES (BM * PAD_K * 2)
#define STG_BYTES (4 * MAT_BYTES)
#define SMEM_GEMM (2 * STG_BYTES)
#define NSTG (D_MODEL / BK)

__global__ __launch_bounds__(256)
void gemm_wmma(const __nv_bfloat16* __restrict__ Ahi, const __nv_bfloat16* __restrict__ Alo,
               const __nv_bfloat16* __restrict__ Bhi, const __nv_bfloat16* __restrict__ Blo,
               float* __restrict__ C, int split_heads)
{
    extern __shared__ char smem[];
    const uint32_t sbase = smem_u32(smem);
    const int tid = threadIdx.x;
    const int wid = tid >> 5;
    const int warp_m = wid & 3;
    const int warp_n = wid >> 2;
    const int m0 = blockIdx.y * BM;
    const int n0 = blockIdx.x * BN;

    auto load_stage = [&](int c, int s) {
        const int k0 = c * BK;
        const uint32_t st = sbase + s * STG_BYTES;
#pragma unroll
        for (int u = 0; u < 2; u++) {
            int idx = tid + u * 256;
            int r   = idx >> 2;
            int c8  = idx & 3;
            uint32_t soff = (uint32_t)(r * (PAD_K * 2) + c8 * 16);
            size_t ga = (size_t)(m0 + r) * D_MODEL + k0 + c8 * 8;
            size_t gb = (size_t)(n0 + r) * D_MODEL + k0 + c8 * 8;
            cp_async16(st + 0 * MAT_BYTES + soff, Ahi + ga);
            cp_async16(st + 1 * MAT_BYTES + soff, Alo + ga);
            cp_async16(st + 2 * MAT_BYTES + soff, Bhi + gb);
            cp_async16(st + 3 * MAT_BYTES + soff, Blo + gb);
        }
        cp_async_commit();
    };

    wmma::fragment<wmma::accumulator, 16, 16, 16, float> acc[2][4];
#pragma unroll
    for (int i = 0; i < 2; i++)
#pragma unroll
        for (int j = 0; j < 4; j++) wmma::fill_fragment(acc[i][j], 0.f);

    load_stage(0, 0);

    for (int c = 0; c < NSTG; c++) {
        const int s = c & 1;
        if (c + 1 < NSTG) load_stage(c + 1, s ^ 1);
        if (c + 1 < NSTG) cp_async_wait<1>(); else cp_async_wait<0>();
        __syncthreads();

        const __nv_bfloat16* sA_hi = (const __nv_bfloat16*)(smem + s * STG_BYTES);
        const __nv_bfloat16* sA_lo = sA_hi + BM * PAD_K;
        const __nv_bfloat16* sB_hi = sA_lo + BM * PAD_K;
        const __nv_bfloat16* sB_lo = sB_hi + BM * PAD_K;

#pragma unroll
        for (int ks = 0; ks < 2; ks++) {
            wmma::fragment<wmma::matrix_a, 16, 16, 16, __nv_bfloat16, wmma::row_major> a_hi[2], a_lo[2];
#pragma unroll
            for (int i = 0; i < 2; i++) {
                int mr = warp_m * 32 + i * 16;
                wmma::load_matrix_sync(a_hi[i], sA_hi + mr * PAD_K + ks * 16, PAD_K);
                wmma::load_matrix_sync(a_lo[i], sA_lo + mr * PAD_K + ks * 16, PAD_K);
            }
#pragma unroll
            for (int j = 0; j < 4; j++) {
                int nr = warp_n * 64 + j * 16;
                wmma::fragment<wmma::matrix_b, 16, 16, 16, __nv_bfloat16, wmma::col_major> b_hi, b_lo;
                wmma::load_matrix_sync(b_hi, sB_hi + nr * PAD_K + ks * 16, PAD_K);
                wmma::load_matrix_sync(b_lo, sB_lo + nr * PAD_K + ks * 16, PAD_K);
#pragma unroll
                for (int i = 0; i < 2; i++) {
                    wmma::mma_sync(acc[i][j], a_hi[i], b_hi, acc[i][j]);
                    wmma::mma_sync(acc[i][j], a_hi[i], b_lo, acc[i][j]);
                    wmma::mma_sync(acc[i][j], a_lo[i], b_hi, acc[i][j]);
                }
            }
        }
        __syncthreads();
    }

    const int b = m0 >> 11;
#pragma unroll
    for (int i = 0; i < 2; i++) {
        int m = m0 + warp_m * 32 + i * 16;
        int sI = m & (S_ - 1);
#pragma unroll
        for (int j = 0; j < 4; j++) {
            int n = n0 + warp_n * 64 + j * 16;
            if (split_heads) {
                int h = n >> 6, d = n & 63;
                float* p = C + (((size_t)b * NUM_HEADS + h) * S_ + sI) * DK + d;
                wmma::store_matrix_sync(p, acc[i][j], DK, wmma::mem_row_major);
            } else {
                float* p = C + (size_t)m * D_MODEL + n;
                wmma::store_matrix_sync(p, acc[i][j], D_MODEL, wmma::mem_row_major);
            }
        }
    }
}

// ===========================================================================
// WMMA bf16x3 causal flash attention, pre-split bf16 inputs + cp.async
// double-buffered K/V. Writes A directly as bf16 hi/lo.
// ===========================================================================
#define PB 72   // bf16 row pad (elems); row pitch 144 B
#define PF 68   // fp32 row pad (elems)
#define TILE_B (64 * PB * 2)     // 9216 bytes per 64x64 bf16 tile
#define KV_STG (4 * TILE_B)      // Khi,Klo,Vhi,Vlo per stage = 36864

#define A_QHI 0
#define A_QLO (A_QHI + TILE_B)
#define A_KV  (A_QLO + TILE_B)               // 2 stages
#define A_PHI (A_KV + 2 * KV_STG)
#define A_PLO (A_PHI + TILE_B)
#define A_SS  (A_PLO + TILE_B)               // fp32 64 x PF
#define A_O   (A_SS + 64 * PF * 4)
#define A_M   (A_O + 64 * PF * 4)
#define A_L   (A_M + 64 * 4)
#define SMEM_ATTN (A_L + 64 * 4)             // 145920

__device__ __forceinline__ void split_store(__nv_bfloat16* hi, __nv_bfloat16* lo,
                                            int off, float v) {
    __nv_bfloat16 h = __float2bfloat16_rn(v);
    hi[off] = h;
    lo[off] = __float2bfloat16_rn(v - __bfloat162float(h));
}

__global__ __launch_bounds__(256)
void attn_wmma(const __nv_bfloat16* __restrict__ Qhi_g, const __nv_bfloat16* __restrict__ Qlo_g,
               const __nv_bfloat16* __restrict__ Khi_g, const __nv_bfloat16* __restrict__ Klo_g,
               const __nv_bfloat16* __restrict__ Vhi_g, const __nv_bfloat16* __restrict__ Vlo_g,
               __nv_bfloat16* __restrict__ Ahi_g, __nv_bfloat16* __restrict__ Alo_g)
{
    extern __shared__ char smem[];
    const uint32_t sbase = smem_u32(smem);
    __nv_bfloat16* Qhi = (__nv_bfloat16*)(smem + A_QHI);
    __nv_bfloat16* Phi = (__nv_bfloat16*)(smem + A_PHI);
    __nv_bfloat16* Plo = (__nv_bfloat16*)(smem + A_PLO);
    float* Ss  = (float*)(smem + A_SS);
    float* Osm = (float*)(smem + A_O);
    float* Msm = (float*)(smem + A_M);
    float* Lsm = (float*)(smem + A_L);

    const int bh = blockIdx.y;
    const int b  = bh >> 4;
    const int h  = bh & 15;
    const size_t hb = (size_t)bh * S_ * DK;

    const int qt  = gridDim.x - 1 - blockIdx.x;   // heavy tiles first
    const int q0  = qt * 64;
    const int tid = threadIdx.x;
    const int wid = tid >> 5;
    const int wm  = (wid & 3) * 16;
    const int wn  = (wid >> 2) * 32;

    // Q tile: 2 matrices x 512 chunks of 16B
#pragma unroll
    for (int u = 0; u < 4; u++) {
        int idx = u * 256 + tid;           // 0..1023
        int mat = idx >> 9;                // 0..1
        int wi  = idx & 511;
        int r   = wi >> 3;
        int c8  = wi & 7;
        const __nv_bfloat16* src = (mat == 0 ? Qhi_g : Qlo_g) + hb + (size_t)(q0 + r) * DK + c8 * 8;
        cp_async16(sbase + A_QHI + mat * TILE_B + r * (PB * 2) + c8 * 16, src);
    }
    cp_async_commit();

    // K/V stage loader: 4 matrices x 512 chunks
    auto load_kv = [&](int kt, int s) {
        const int k0 = kt * 64;
        const uint32_t st = sbase + A_KV + s * KV_STG;
#pragma unroll
        for (int u = 0; u < 8; u++) {
            int idx = u * 256 + tid;       // 0..2047
            int mat = idx >> 9;            // 0..3
            int wi  = idx & 511;
            int r   = wi >> 3;
            int c8  = wi & 7;
            const __nv_bfloat16* base =
                mat == 0 ? Khi_g : mat == 1 ? Klo_g : mat == 2 ? Vhi_g : Vlo_g;
            cp_async16(st + mat * TILE_B + r * (PB * 2) + c8 * 16,
                       base + hb + (size_t)(k0 + r) * DK + c8 * 8);
        }
        cp_async_commit();
    };

    for (int i = tid; i < 64 * PF; i += 256) Osm[i] = 0.f;
    if (tid < 64) { Msm[tid] = -1e30f; Lsm[tid] = 0.f; }

    load_kv(0, 0);

    const int row = tid >> 2;
    const int qq  = tid & 3;
    const float scale = 0.125f;

    for (int kt = 0; kt <= qt; kt++) {
        const int k0 = kt * 64;
        const int s  = kt & 1;
        if (kt + 1 <= qt) load_kv(kt + 1, s ^ 1);
        if (kt + 1 <= qt) cp_async_wait<1>(); else cp_async_wait<0>();
        __syncthreads();   // (A) Q + stage s ready; prev iter's O+= done

        const __nv_bfloat16* Khi = (const __nv_bfloat16*)(smem + A_KV + s * KV_STG);
        const __nv_bfloat16* Klo = Khi + 64 * PB;
        const __nv_bfloat16* Vhi = Klo + 64 * PB;
        const __nv_bfloat16* Vlo = Vhi + 64 * PB;
        __nv_bfloat16* Qlo = (__nv_bfloat16*)(smem + A_QLO);

        // ---- S = Q K^T (bf16x3) ----
        {
            wmma::fragment<wmma::accumulator, 16, 16, 16, float> sfr[2];
            wmma::fill_fragment(sfr[0], 0.f);
            wmma::fill_fragment(sfr[1], 0.f);
#pragma unroll
            for (int dk = 0; dk < 4; dk++) {
                wmma::fragment<wmma::matrix_a, 16, 16, 16, __nv_bfloat16, wmma::row_major> ah, al;
                wmma::load_matrix_sync(ah, Qhi + wm * PB + dk * 16, PB);
                wmma::load_matrix_sync(al, Qlo + wm * PB + dk * 16, PB);
#pragma unroll
                for (int j = 0; j < 2; j++) {
                    wmma::fragment<wmma::matrix_b, 16, 16, 16, __nv_bfloat16, wmma::col_major> bh_, bl_;
                    wmma::load_matrix_sync(bh_, Khi + (wn + j * 16) * PB + dk * 16, PB);
                    wmma::load_matrix_sync(bl_, Klo + (wn + j * 16) * PB + dk * 16, PB);
                    wmma::mma_sync(sfr[j], ah, bh_, sfr[j]);
                    wmma::mma_sync(sfr[j], ah, bl_, sfr[j]);
                    wmma::mma_sync(sfr[j], al, bh_, sfr[j]);
                }
            }
            wmma::store_matrix_sync(Ss + wm * PF + wn,      sfr[0], PF, wmma::mem_row_major);
            wmma::store_matrix_sync(Ss + wm * PF + wn + 16, sfr[1], PF, wmma::mem_row_major);
        }
        __syncthreads();   // (B) S staged

        // ---- softmax (4 threads/row) ----
        {
            const bool diag = (kt == qt);
            const int qrow = q0 + row;
            float sv[16];
            float vmax = -1e30f;
#pragma unroll
            for (int c = 0; c < 16; c++) {
                int col = qq * 16 + c;
                float v = Ss[row * PF + col] * scale;
                if (diag && (k0 + col > qrow)) v = -1e30f;
                sv[c] = v;
                vmax = fmaxf(vmax, v);
            }
            vmax = fmaxf(vmax, __shfl_xor_sync(0xffffffffu, vmax, 1, 4));
            vmax = fmaxf(vmax, __shfl_xor_sync(0xffffffffu, vmax, 2, 4));

            float mprev = Msm[row];
            float newm  = fmaxf(mprev, vmax);
            float corr  = __expf(mprev - newm);
            float rsum  = 0.f;
#pragma unroll
            for (int c = 0; c < 16; c++) {
                float p = __expf(sv[c] - newm);
                rsum += p;
                split_store(Phi, Plo, row * PB + qq * 16 + c, p);
            }
            rsum += __shfl_xor_sync(0xffffffffu, rsum, 1, 4);
            rsum += __shfl_xor_sync(0xffffffffu, rsum, 2, 4);
            if (qq == 0) {
                Msm[row] = newm;
                Lsm[row] = Lsm[row] * corr + rsum;
            }
#pragma unroll
            for (int c = 0; c < 16; c++)
                Osm[row * PF + qq * 16 + c] *= corr;
        }
        __syncthreads();   // (C) P ready, O rescaled

        // ---- PV (bf16x3) -> Ss scratch ----
        {
            wmma::fragment<wmma::accumulator, 16, 16, 16, float> ofr[2];
            wmma::fill_fragment(ofr[0], 0.f);
            wmma::fill_fragment(ofr[1], 0.f);
#pragma unroll
            for (int dk = 0; dk < 4; dk++) {
                wmma::fragment<wmma::matrix_a, 16, 16, 16, __nv_bfloat16, wmma::row_major> ah, al;
                wmma::load_matrix_sync(ah, Phi + wm * PB + dk * 16, PB);
                wmma::load_matrix_sync(al, Plo + wm * PB + dk * 16, PB);
#pragma unroll
                for (int j = 0; j < 2; j++) {
                    wmma::fragment<wmma::matrix_b, 16, 16, 16, __nv_bfloat16, wmma::row_major> bh_, bl_;
                    wmma::load_matrix_sync(bh_, Vhi + (dk * 16) * PB + wn + j * 16, PB);
                    wmma::load_matrix_sync(bl_, Vlo + (dk * 16) * PB + wn + j * 16, PB);
                    wmma::mma_sync(ofr[j], ah, bh_, ofr[j]);
                    wmma::mma_sync(ofr[j], ah, bl_, ofr[j]);
                    wmma::mma_sync(ofr[j], al, bh_, ofr[j]);
                }
            }
            wmma::store_matrix_sync(Ss + wm * PF + wn,      ofr[0], PF, wmma::mem_row_major);
            wmma::store_matrix_sync(Ss + wm * PF + wn + 16, ofr[1], PF, wmma::mem_row_major);
        }
        __syncthreads();   // (D) PV staged; V reads complete

        // ---- O += PV ----
#pragma unroll
        for (int c = 0; c < 16; c++)
            Osm[row * PF + qq * 16 + c] += Ss[row * PF + qq * 16 + c];
    }
    __syncthreads();

    // epilogue: normalize, split-store to Ahi/Alo in [B,S,D]
    {
        float inv_l = 1.f / Lsm[row];
        size_t base = ((size_t)b * S_ + q0 + row) * D_MODEL + h * DK + qq * 16;
#pragma unroll
        for (int c = 0; c < 16; c++) {
            float v = Osm[row * PF + qq * 16 + c] * inv_l;
            __nv_bfloat16 hv = __float2bfloat16_rn(v);
            Ahi_g[base + c] = hv;
            Alo_g[base + c] = __float2bfloat16_rn(v - __bfloat162float(hv));
        }
    }
}

// ===========================================================================
// Launch
// ===========================================================================
extern "C" void kernel_launch(void* const* d_in, const int* in_sizes, int n_in,
                              void* d_out, int out_size)
{
    (void)in_sizes; (void)n_in; (void)out_size;
    const float* x  = (const float*)d_in[0];
    const float* Wq = (const float*)d_in[1];
    const float* Wk = (const float*)d_in[2];
    const float* Wv = (const float*)d_in[3];
    const float* Wo = (const float*)d_in[4];
    float* out = (float*)d_out;

    float *pQ, *pK, *pV;
    __nv_bfloat16 *pxh, *pxl, *pWh, *pWl, *pAh, *pAl;
    __nv_bfloat16 *pQh, *pQl, *pKh, *pKl, *pVh, *pVl;
    cudaGetSymbolAddress((void**)&pQ,  g_Q);
    cudaGetSymbolAddress((void**)&pK,  g_K);
    cudaGetSymbolAddress((void**)&pV,  g_V);
    cudaGetSymbolAddress((void**)&pxh, g_xhi);
    cudaGetSymbolAddress((void**)&pxl, g_xlo);
    cudaGetSymbolAddress((void**)&pWh, g_Whi);
    cudaGetSymbolAddress((void**)&pWl, g_Wlo);
    cudaGetSymbolAddress((void**)&pAh, g_Ahi);
    cudaGetSymbolAddress((void**)&pAl, g_Alo);
    cudaGetSymbolAddress((void**)&pQh, g_Qhi);
    cudaGetSymbolAddress((void**)&pQl, g_Qlo);
    cudaGetSymbolAddress((void**)&pKh, g_Khi);
    cudaGetSymbolAddress((void**)&pKl, g_Klo);
    cudaGetSymbolAddress((void**)&pVh, g_Vhi);
    cudaGetSymbolAddress((void**)&pVl, g_Vlo);

    cudaFuncSetAttribute(gemm_wmma, cudaFuncAttributeMaxDynamicSharedMemorySize,
                         SMEM_GEMM);
    cudaFuncSetAttribute(attn_wmma, cudaFuncAttributeMaxDynamicSharedMemorySize,
                         SMEM_ATTN);

    const size_t WSZ = (size_t)D_MODEL * D_MODEL;
    const int nx4 = M_ROWS * D_MODEL / 4;
    const int nw4 = (int)(WSZ / 4);

    split_fp32<<<nx4 / 256, 256>>>(x,  pxh, pxl, nx4);
    split_fp32<<<nw4 / 256, 256>>>(Wq, pWh + 0 * WSZ, pWl + 0 * WSZ, nw4);
    split_fp32<<<nw4 / 256, 256>>>(Wk, pWh + 1 * WSZ, pWl + 1 * WSZ, nw4);
    split_fp32<<<nw4 / 256, 256>>>(Wv, pWh + 2 * WSZ, pWl + 2 * WSZ, nw4);
    split_fp32<<<nw4 / 256, 256>>>(Wo, pWh + 3 * WSZ, pWl + 3 * WSZ, nw4);

    dim3 ggrid(D_MODEL / BN, M_ROWS / BM);
    gemm_wmma<<<ggrid, 256, SMEM_GEMM>>>(pxh, pxl, pWh + 0 * WSZ, pWl + 0 * WSZ, pQ, 1);
    gemm_wmma<<<ggrid, 256, SMEM_GEMM>>>(pxh, pxl, pWh + 1 * WSZ, pWl + 1 * WSZ, pK, 1);
    gemm_wmma<<<ggrid, 256, SMEM_GEMM>>>(pxh, pxl, pWh + 2 * WSZ, pWl + 2 * WSZ, pV, 1);

    // one-time splits of head-major Q,K,V
    split_fp32<<<nx4 / 256, 256>>>(pQ, pQh, pQl, nx4);
    split_fp32<<<nx4 / 256, 256>>>(pK, pKh, pKl, nx4);
    split_fp32<<<nx4 / 256, 256>>>(pV, pVh, pVl, nx4);

    dim3 agrid(S_ / 64, B_ * NUM_HEADS);
    attn_wmma<<<agrid, 256, SMEM_ATTN>>>(pQh, pQl, pKh, pKl, pVh, pVl, pAh, pAl);

    gemm_wmma<<<ggrid, 256, SMEM_GEMM>>>(pAh, pAl, pWh + 3 * WSZ, pWl + 3 * WSZ, out, 0);
}

// round 6
// speedup vs baseline: 1.4407x; 1.4407x over previous
#include <cuda_runtime.h>
#include <cuda_bf16.h>
#include <mma.h>
#include <math.h>
#include <stdint.h>

using namespace nvcuda;

// Problem constants
#define D_MODEL   1024
#define NUM_HEADS 16
#define DK        64
#define B_        2
#define S_        2048
#define M_ROWS    (B_ * S_)   // 4096

// ===========================================================================
// Scratch (__device__ globals, allocation-free)
// ===========================================================================
__device__ __align__(128) float g_Q[(size_t)M_ROWS * D_MODEL];
__device__ __align__(128) float g_K[(size_t)M_ROWS * D_MODEL];
__device__ __align__(128) float g_V[(size_t)M_ROWS * D_MODEL];

__device__ __align__(128) __nv_bfloat16 g_xhi[(size_t)M_ROWS * D_MODEL];
__device__ __align__(128) __nv_bfloat16 g_xlo[(size_t)M_ROWS * D_MODEL];
__device__ __align__(128) __nv_bfloat16 g_Whi[4][(size_t)D_MODEL * D_MODEL];
__device__ __align__(128) __nv_bfloat16 g_Wlo[4][(size_t)D_MODEL * D_MODEL];
__device__ __align__(128) __nv_bfloat16 g_Ahi[(size_t)M_ROWS * D_MODEL];
__device__ __align__(128) __nv_bfloat16 g_Alo[(size_t)M_ROWS * D_MODEL];

// head-major bf16 hi/lo Q,K,V
__device__ __align__(128) __nv_bfloat16 g_Qhi[(size_t)M_ROWS * D_MODEL];
__device__ __align__(128) __nv_bfloat16 g_Qlo[(size_t)M_ROWS * D_MODEL];
__device__ __align__(128) __nv_bfloat16 g_Khi[(size_t)M_ROWS * D_MODEL];
__device__ __align__(128) __nv_bfloat16 g_Klo[(size_t)M_ROWS * D_MODEL];
__device__ __align__(128) __nv_bfloat16 g_Vhi[(size_t)M_ROWS * D_MODEL];
__device__ __align__(128) __nv_bfloat16 g_Vlo[(size_t)M_ROWS * D_MODEL];

// ===========================================================================
// helpers
// ===========================================================================
__device__ __forceinline__ uint32_t smem_u32(const void* p) {
    uint32_t a;
    asm("{ .reg .u64 t; cvta.to.shared.u64 t, %1; cvt.u32.u64 %0, t; }"
        : "=r"(a) : "l"(p));
    return a;
}
__device__ __forceinline__ void cp_async16(uint32_t dst, const void* src) {
    uint64_t gsrc = __cvta_generic_to_global(src);
    asm volatile("cp.async.cg.shared.global [%0], [%1], 16;" :: "r"(dst), "l"(gsrc));
}
__device__ __forceinline__ void cp_async_commit() {
    asm volatile("cp.async.commit_group;" ::: "memory");
}
template <int N>
__device__ __forceinline__ void cp_async_wait() {
    asm volatile("cp.async.wait_group %0;" :: "n"(N) : "memory");
}
__device__ __forceinline__ void ldsm_x4(uint32_t r[4], uint32_t addr) {
    asm volatile("ldmatrix.sync.aligned.m8n8.x4.shared.b16 {%0,%1,%2,%3}, [%4];"
                 : "=r"(r[0]), "=r"(r[1]), "=r"(r[2]), "=r"(r[3]) : "r"(addr));
}
__device__ __forceinline__ void ldsm_x4_t(uint32_t r[4], uint32_t addr) {
    asm volatile("ldmatrix.sync.aligned.m8n8.x4.trans.shared.b16 {%0,%1,%2,%3}, [%4];"
                 : "=r"(r[0]), "=r"(r[1]), "=r"(r[2]), "=r"(r[3]) : "r"(addr));
}
__device__ __forceinline__ void mma16816(float c[4], const uint32_t a[4], const uint32_t b[2]) {
    asm volatile("mma.sync.aligned.m16n8k16.row.col.f32.bf16.bf16.f32 "
                 "{%0,%1,%2,%3}, {%4,%5,%6,%7}, {%8,%9}, {%0,%1,%2,%3};"
                 : "+f"(c[0]), "+f"(c[1]), "+f"(c[2]), "+f"(c[3])
                 : "r"(a[0]), "r"(a[1]), "r"(a[2]), "r"(a[3]), "r"(b[0]), "r"(b[1]));
}
__device__ __forceinline__ void pack_hl(float x, float y, uint32_t& hv, uint32_t& lv) {
    __nv_bfloat162 h = __float22bfloat162_rn(make_float2(x, y));
    float2 hf = __bfloat1622float2(h);
    __nv_bfloat162 l = __float22bfloat162_rn(make_float2(x - hf.x, y - hf.y));
    hv = *reinterpret_cast<uint32_t*>(&h);
    lv = *reinterpret_cast<uint32_t*>(&l);
}

// ===========================================================================
// fp32 -> (bf16 hi, bf16 lo) split
// ===========================================================================
__global__ __launch_bounds__(256)
void split_fp32(const float* __restrict__ in, __nv_bfloat16* __restrict__ hi,
                __nv_bfloat16* __restrict__ lo, int n4)
{
    int i = blockIdx.x * 256 + threadIdx.x;
    if (i >= n4) return;
    float4 v = ((const float4*)in)[i];
    __nv_bfloat16 h0 = __float2bfloat16_rn(v.x);
    __nv_bfloat16 h1 = __float2bfloat16_rn(v.y);
    __nv_bfloat16 h2 = __float2bfloat16_rn(v.z);
    __nv_bfloat16 h3 = __float2bfloat16_rn(v.w);
    __nv_bfloat16 l0 = __float2bfloat16_rn(v.x - __bfloat162float(h0));
    __nv_bfloat16 l1 = __float2bfloat16_rn(v.y - __bfloat162float(h1));
    __nv_bfloat16 l2 = __float2bfloat16_rn(v.z - __bfloat162float(h2));
    __nv_bfloat16 l3 = __float2bfloat16_rn(v.w - __bfloat162float(h3));
    ((__nv_bfloat162*)hi)[i * 2 + 0] = __nv_bfloat162(h0, h1);
    ((__nv_bfloat162*)hi)[i * 2 + 1] = __nv_bfloat162(h2, h3);
    ((__nv_bfloat162*)lo)[i * 2 + 0] = __nv_bfloat162(l0, l1);
    ((__nv_bfloat162*)lo)[i * 2 + 1] = __nv_bfloat162(l2, l3);
}

// ===========================================================================
// WMMA bf16x3 GEMM (unchanged from R3)
// ===========================================================================
#define BM 128
#define BN 128
#define BK 32
#define PAD_K 40
#define MAT_BYTES (BM * PAD_K * 2)
#define STG_BYTES (4 * MAT_BYTES)
#define SMEM_GEMM (2 * STG_BYTES)
#define NSTG (D_MODEL / BK)

__global__ __launch_bounds__(256)
void gemm_wmma(const __nv_bfloat16* __restrict__ Ahi, const __nv_bfloat16* __restrict__ Alo,
               const __nv_bfloat16* __restrict__ Bhi, const __nv_bfloat16* __restrict__ Blo,
               float* __restrict__ C, int split_heads)
{
    extern __shared__ char smem[];
    const uint32_t sbase = smem_u32(smem);
    const int tid = threadIdx.x;
    const int wid = tid >> 5;
    const int warp_m = wid & 3;
    const int warp_n = wid >> 2;
    const int m0 = blockIdx.y * BM;
    const int n0 = blockIdx.x * BN;

    auto load_stage = [&](int c, int s) {
        const int k0 = c * BK;
        const uint32_t st = sbase + s * STG_BYTES;
#pragma unroll
        for (int u = 0; u < 2; u++) {
            int idx = tid + u * 256;
            int r   = idx >> 2;
            int c8  = idx & 3;
            uint32_t soff = (uint32_t)(r * (PAD_K * 2) + c8 * 16);
            size_t ga = (size_t)(m0 + r) * D_MODEL + k0 + c8 * 8;
            size_t gb = (size_t)(n0 + r) * D_MODEL + k0 + c8 * 8;
            cp_async16(st + 0 * MAT_BYTES + soff, Ahi + ga);
            cp_async16(st + 1 * MAT_BYTES + soff, Alo + ga);
            cp_async16(st + 2 * MAT_BYTES + soff, Bhi + gb);
            cp_async16(st + 3 * MAT_BYTES + soff, Blo + gb);
        }
        cp_async_commit();
    };

    wmma::fragment<wmma::accumulator, 16, 16, 16, float> acc[2][4];
#pragma unroll
    for (int i = 0; i < 2; i++)
#pragma unroll
        for (int j = 0; j < 4; j++) wmma::fill_fragment(acc[i][j], 0.f);

    load_stage(0, 0);

    for (int c = 0; c < NSTG; c++) {
        const int s = c & 1;
        if (c + 1 < NSTG) load_stage(c + 1, s ^ 1);
        if (c + 1 < NSTG) cp_async_wait<1>(); else cp_async_wait<0>();
        __syncthreads();

        const __nv_bfloat16* sA_hi = (const __nv_bfloat16*)(smem + s * STG_BYTES);
        const __nv_bfloat16* sA_lo = sA_hi + BM * PAD_K;
        const __nv_bfloat16* sB_hi = sA_lo + BM * PAD_K;
        const __nv_bfloat16* sB_lo = sB_hi + BM * PAD_K;

#pragma unroll
        for (int ks = 0; ks < 2; ks++) {
            wmma::fragment<wmma::matrix_a, 16, 16, 16, __nv_bfloat16, wmma::row_major> a_hi[2], a_lo[2];
#pragma unroll
            for (int i = 0; i < 2; i++) {
                int mr = warp_m * 32 + i * 16;
                wmma::load_matrix_sync(a_hi[i], sA_hi + mr * PAD_K + ks * 16, PAD_K);
                wmma::load_matrix_sync(a_lo[i], sA_lo + mr * PAD_K + ks * 16, PAD_K);
            }
#pragma unroll
            for (int j = 0; j < 4; j++) {
                int nr = warp_n * 64 + j * 16;
                wmma::fragment<wmma::matrix_b, 16, 16, 16, __nv_bfloat16, wmma::col_major> b_hi, b_lo;
                wmma::load_matrix_sync(b_hi, sB_hi + nr * PAD_K + ks * 16, PAD_K);
                wmma::load_matrix_sync(b_lo, sB_lo + nr * PAD_K + ks * 16, PAD_K);
#pragma unroll
                for (int i = 0; i < 2; i++) {
                    wmma::mma_sync(acc[i][j], a_hi[i], b_hi, acc[i][j]);
                    wmma::mma_sync(acc[i][j], a_hi[i], b_lo, acc[i][j]);
                    wmma::mma_sync(acc[i][j], a_lo[i], b_hi, acc[i][j]);
                }
            }
        }
        __syncthreads();
    }

    const int b = m0 >> 11;
#pragma unroll
    for (int i = 0; i < 2; i++) {
        int m = m0 + warp_m * 32 + i * 16;
        int sI = m & (S_ - 1);
#pragma unroll
        for (int j = 0; j < 4; j++) {
            int n = n0 + warp_n * 64 + j * 16;
            if (split_heads) {
                int h = n >> 6, d = n & 63;
                float* p = C + (((size_t)b * NUM_HEADS + h) * S_ + sI) * DK + d;
                wmma::store_matrix_sync(p, acc[i][j], DK, wmma::mem_row_major);
            } else {
                float* p = C + (size_t)m * D_MODEL + n;
                wmma::store_matrix_sync(p, acc[i][j], D_MODEL, wmma::mem_row_major);
            }
        }
    }
}

// ===========================================================================
// Register-resident FA2, raw mma.sync m16n8k16, bf16x3.
// Block = 128 q-rows x 8 warps (16 rows/warp). K/V double-buffered cp.async.
// ===========================================================================
#define QROWS 128
#define KTILE 64
#define PITCH 144                     // bytes per smem row (72 bf16)
#define Q_BYTES (QROWS * PITCH)       // 18432 per matrix (hi / lo)
#define KV_MAT (KTILE * PITCH)        // 9216 per 64x64 tile
#define KV_STG2 (4 * KV_MAT)          // 36864 per stage (Khi,Klo,Vhi,Vlo)
#define AT_Q 0
#define AT_KV (2 * Q_BYTES)           // 36864
#define SMEM_ATTN (AT_KV + 2 * KV_STG2)   // 110592

__global__ void __launch_bounds__(256)
attn_mma(const __nv_bfloat16* __restrict__ Qhi_g, const __nv_bfloat16* __restrict__ Qlo_g,
         const __nv_bfloat16* __restrict__ Khi_g, const __nv_bfloat16* __restrict__ Klo_g,
         const __nv_bfloat16* __restrict__ Vhi_g, const __nv_bfloat16* __restrict__ Vlo_g,
         __nv_bfloat16* __restrict__ Ahi_g, __nv_bfloat16* __restrict__ Alo_g)
{
    extern __shared__ char smem[];
    const uint32_t sbase = smem_u32(smem);
    const int tid  = threadIdx.x;
    const int wid  = tid >> 5;
    const int lane = tid & 31;
    const int g    = lane >> 3;
    const int li   = lane & 7;

    const int bh = blockIdx.y;
    const int b  = bh >> 4;
    const int h  = bh & 15;
    const size_t hb = (size_t)bh * S_ * DK;

    const int qt = gridDim.x - 1 - blockIdx.x;   // heavy tiles first
    const int q0 = qt * QROWS;
    const int wm = wid * 16;
    const int wrmax = q0 + wm + 15;

    // ---- prologue: cp.async Q(hi,lo) + KV stage 0 ----
#pragma unroll
    for (int u = 0; u < 8; u++) {
        int idx = u * 256 + tid;        // 0..2047
        int mat = idx >> 10;            // 0..1
        int wi  = idx & 1023;
        int r   = wi >> 3;
        int c8  = wi & 7;
        const __nv_bfloat16* src = (mat == 0 ? Qhi_g : Qlo_g) + hb + (size_t)(q0 + r) * DK + c8 * 8;
        cp_async16(sbase + AT_Q + mat * Q_BYTES + r * PITCH + c8 * 16, src);
    }
    cp_async_commit();

    auto load_kv = [&](int kt, int s) {
        const int k0 = kt * KTILE;
        const uint32_t st = sbase + AT_KV + s * KV_STG2;
#pragma unroll
        for (int u = 0; u < 8; u++) {
            int idx = u * 256 + tid;    // 0..2047
            int mat = idx >> 9;         // 0..3
            int wi  = idx & 511;
            int r   = wi >> 3;
            int c8  = wi & 7;
            const __nv_bfloat16* base =
                mat == 0 ? Khi_g : mat == 1 ? Klo_g : mat == 2 ? Vhi_g : Vlo_g;
            cp_async16(st + mat * KV_MAT + r * PITCH + c8 * 16,
                       base + hb + (size_t)(k0 + r) * DK + c8 * 8);
        }
        cp_async_commit();
    };

    load_kv(0, 0);
    cp_async_wait<0>();
    __syncthreads();

    // ---- Q fragments (registers, reused across all k-tiles) ----
    uint32_t qh[4][4], ql[4][4];
    {
        const uint32_t rowb = sbase + AT_Q + (uint32_t)(wm + ((g & 1) << 3) + li) * PITCH
                              + ((uint32_t)(g >> 1) << 4);
#pragma unroll
        for (int ks = 0; ks < 4; ks++) {
            ldsm_x4(qh[ks], rowb + ks * 32);
            ldsm_x4(ql[ks], rowb + ks * 32 + Q_BYTES);
        }
    }

    float Oc[8][4];
#pragma unroll
    for (int j = 0; j < 8; j++)
#pragma unroll
        for (int e = 0; e < 4; e++) Oc[j][e] = 0.f;
    float m0v = -1e30f, m1v = -1e30f, l0v = 0.f, l1v = 0.f;

    const int r0g = q0 + wm + (lane >> 2);   // global row (lanes' quad row)
    const int r1g = r0g + 8;
    const int nkt = 2 * qt + 2;

    for (int kt = 0; kt < nkt; kt++) {
        const int s  = kt & 1;
        const int k0 = kt * KTILE;
        if (kt + 1 < nkt) load_kv(kt + 1, s ^ 1);
        if (kt + 1 < nkt) cp_async_wait<1>(); else cp_async_wait<0>();
        __syncthreads();   // stage s visible to all

        if (k0 <= wrmax) {
            const uint32_t kb = sbase + AT_KV + s * KV_STG2;       // Khi base

            // ---- S = Q K^T (registers) ----
            float Sc[8][4];
#pragma unroll
            for (int j = 0; j < 8; j++)
#pragma unroll
                for (int e = 0; e < 4; e++) Sc[j][e] = 0.f;

#pragma unroll
            for (int ks = 0; ks < 4; ks++) {
#pragma unroll
                for (int jp = 0; jp < 4; jp++) {
                    uint32_t bh4[4], bl4[4];
                    uint32_t addr = kb + (uint32_t)(jp * 16 + ((g >> 1) << 3) + li) * PITCH
                                    + ks * 32 + ((uint32_t)(g & 1) << 4);
                    ldsm_x4(bh4, addr);
                    ldsm_x4(bl4, addr + KV_MAT);
                    mma16816(Sc[2 * jp],     qh[ks], bh4 + 0);
                    mma16816(Sc[2 * jp],     qh[ks], bl4 + 0);
                    mma16816(Sc[2 * jp],     ql[ks], bh4 + 0);
                    mma16816(Sc[2 * jp + 1], qh[ks], bh4 + 2);
                    mma16816(Sc[2 * jp + 1], qh[ks], bl4 + 2);
                    mma16816(Sc[2 * jp + 1], ql[ks], bh4 + 2);
                }
            }

            // ---- softmax in registers ----
            float rx0 = -1e30f, rx1 = -1e30f;
#pragma unroll
            for (int j = 0; j < 8; j++) {
                int cb = k0 + 8 * j + 2 * (lane & 3);
#pragma unroll
                for (int e = 0; e < 2; e++) {
                    float v0 = Sc[j][e] * 0.125f;
                    float v1 = Sc[j][2 + e] * 0.125f;
                    if (cb + e > r0g) v0 = -1e30f;
                    if (cb + e > r1g) v1 = -1e30f;
                    Sc[j][e] = v0; Sc[j][2 + e] = v1;
                    rx0 = fmaxf(rx0, v0); rx1 = fmaxf(rx1, v1);
                }
            }
            rx0 = fmaxf(rx0, __shfl_xor_sync(0xffffffffu, rx0, 1, 4));
            rx0 = fmaxf(rx0, __shfl_xor_sync(0xffffffffu, rx0, 2, 4));
            rx1 = fmaxf(rx1, __shfl_xor_sync(0xffffffffu, rx1, 1, 4));
            rx1 = fmaxf(rx1, __shfl_xor_sync(0xffffffffu, rx1, 2, 4));

            float nm0 = fmaxf(m0v, rx0), nm1 = fmaxf(m1v, rx1);
            float cr0 = __expf(m0v - nm0), cr1 = __expf(m1v - nm1);
            float s0 = 0.f, s1 = 0.f;
#pragma unroll
            for (int j = 0; j < 8; j++) {
#pragma unroll
                for (int e = 0; e < 2; e++) {
                    float p0 = __expf(Sc[j][e] - nm0);
                    float p1 = __expf(Sc[j][2 + e] - nm1);
                    Sc[j][e] = p0; Sc[j][2 + e] = p1;
                    s0 += p0; s1 += p1;
                }
            }
            s0 += __shfl_xor_sync(0xffffffffu, s0, 1, 4);
            s0 += __shfl_xor_sync(0xffffffffu, s0, 2, 4);
            s1 += __shfl_xor_sync(0xffffffffu, s1, 1, 4);
            s1 += __shfl_xor_sync(0xffffffffu, s1, 2, 4);
            l0v = l0v * cr0 + s0;  l1v = l1v * cr1 + s1;
            m0v = nm0;  m1v = nm1;
#pragma unroll
            for (int j = 0; j < 8; j++) {
                Oc[j][0] *= cr0; Oc[j][1] *= cr0;
                Oc[j][2] *= cr1; Oc[j][3] *= cr1;
            }

            // ---- P -> A fragments (hi/lo) ----
            uint32_t ph[4][4], pl[4][4];
#pragma unroll
            for (int ks = 0; ks < 4; ks++) {
                int j0 = 2 * ks, j1 = 2 * ks + 1;
                pack_hl(Sc[j0][0], Sc[j0][1], ph[ks][0], pl[ks][0]);
                pack_hl(Sc[j0][2], Sc[j0][3], ph[ks][1], pl[ks][1]);
                pack_hl(Sc[j1][0], Sc[j1][1], ph[ks][2], pl[ks][2]);
                pack_hl(Sc[j1][2], Sc[j1][3], ph[ks][3], pl[ks][3]);
            }

            // ---- O += P V ----
            const uint32_t vb = kb + 2 * KV_MAT;   // Vhi base
#pragma unroll
            for (int ks = 0; ks < 4; ks++) {
#pragma unroll
                for (int jp = 0; jp < 4; jp++) {
                    uint32_t vh4[4], vl4[4];
                    uint32_t addr = vb + (uint32_t)(ks * 16 + ((g & 1) << 3) + li) * PITCH
                                    + jp * 32 + ((uint32_t)(g >> 1) << 4);
                    ldsm_x4_t(vh4, addr);
                    ldsm_x4_t(vl4, addr + KV_MAT);
                    mma16816(Oc[2 * jp],     ph[ks], vh4 + 0);
                    mma16816(Oc[2 * jp],     ph[ks], vl4 + 0);
                    mma16816(Oc[2 * jp],     pl[ks], vh4 + 0);
                    mma16816(Oc[2 * jp + 1], ph[ks], vh4 + 2);
                    mma16816(Oc[2 * jp + 1], ph[ks], vl4 + 2);
                    mma16816(Oc[2 * jp + 1], pl[ks], vh4 + 2);
                }
            }
        }
        __syncthreads();   // all reads of stage s done before it is overwritten
    }

    // ---- epilogue: normalize, split-store bf16 hi/lo to A [B,S,D] ----
    {
        float il0 = 1.f / l0v, il1 = 1.f / l1v;
        size_t base0 = ((size_t)b * S_ + r0g) * D_MODEL + h * DK + 2 * (lane & 3);
        size_t base1 = ((size_t)b * S_ + r1g) * D_MODEL + h * DK + 2 * (lane & 3);
#pragma unroll
        for (int j = 0; j < 8; j++) {
            uint32_t hv, lv;
            pack_hl(Oc[j][0] * il0, Oc[j][1] * il0, hv, lv);
            *reinterpret_cast<uint32_t*>(Ahi_g + base0 + 8 * j) = hv;
            *reinterpret_cast<uint32_t*>(Alo_g + base0 + 8 * j) = lv;
            pack_hl(Oc[j][2] * il1, Oc[j][3] * il1, hv, lv);
            *reinterpret_cast<uint32_t*>(Ahi_g + base1 + 8 * j) = hv;
            *reinterpret_cast<uint32_t*>(Alo_g + base1 + 8 * j) = lv;
        }
    }
}

// ===========================================================================
// Launch
// ===========================================================================
extern "C" void kernel_launch(void* const* d_in, const int* in_sizes, int n_in,
                              void* d_out, int out_size)
{
    (void)in_sizes; (void)n_in; (void)out_size;
    const float* x  = (const float*)d_in[0];
    const float* Wq = (const float*)d_in[1];
    const float* Wk = (const float*)d_in[2];
    const float* Wv = (const float*)d_in[3];
    const float* Wo = (const float*)d_in[4];
    float* out = (float*)d_out;

    float *pQ, *pK, *pV;
    __nv_bfloat16 *pxh, *pxl, *pWh, *pWl, *pAh, *pAl;
    __nv_bfloat16 *pQh, *pQl, *pKh, *pKl, *pVh, *pVl;
    cudaGetSymbolAddress((void**)&pQ,  g_Q);
    cudaGetSymbolAddress((void**)&pK,  g_K);
    cudaGetSymbolAddress((void**)&pV,  g_V);
    cudaGetSymbolAddress((void**)&pxh, g_xhi);
    cudaGetSymbolAddress((void**)&pxl, g_xlo);
    cudaGetSymbolAddress((void**)&pWh, g_Whi);
    cudaGetSymbolAddress((void**)&pWl, g_Wlo);
    cudaGetSymbolAddress((void**)&pAh, g_Ahi);
    cudaGetSymbolAddress((void**)&pAl, g_Alo);
    cudaGetSymbolAddress((void**)&pQh, g_Qhi);
    cudaGetSymbolAddress((void**)&pQl, g_Qlo);
    cudaGetSymbolAddress((void**)&pKh, g_Khi);
    cudaGetSymbolAddress((void**)&pKl, g_Klo);
    cudaGetSymbolAddress((void**)&pVh, g_Vhi);
    cudaGetSymbolAddress((void**)&pVl, g_Vlo);

    cudaFuncSetAttribute(gemm_wmma, cudaFuncAttributeMaxDynamicSharedMemorySize,
                         SMEM_GEMM);
    cudaFuncSetAttribute(attn_mma, cudaFuncAttributeMaxDynamicSharedMemorySize,
                         SMEM_ATTN);

    const size_t WSZ = (size_t)D_MODEL * D_MODEL;
    const int nx4 = M_ROWS * D_MODEL / 4;
    const int nw4 = (int)(WSZ / 4);

    split_fp32<<<nx4 / 256, 256>>>(x,  pxh, pxl, nx4);
    split_fp32<<<nw4 / 256, 256>>>(Wq, pWh + 0 * WSZ, pWl + 0 * WSZ, nw4);
    split_fp32<<<nw4 / 256, 256>>>(Wk, pWh + 1 * WSZ, pWl + 1 * WSZ, nw4);
    split_fp32<<<nw4 / 256, 256>>>(Wv, pWh + 2 * WSZ, pWl + 2 * WSZ, nw4);
    split_fp32<<<nw4 / 256, 256>>>(Wo, pWh + 3 * WSZ, pWl + 3 * WSZ, nw4);

    dim3 ggrid(D_MODEL / BN, M_ROWS / BM);
    gemm_wmma<<<ggrid, 256, SMEM_GEMM>>>(pxh, pxl, pWh + 0 * WSZ, pWl + 0 * WSZ, pQ, 1);
    gemm_wmma<<<ggrid, 256, SMEM_GEMM>>>(pxh, pxl, pWh + 1 * WSZ, pWl + 1 * WSZ, pK, 1);
    gemm_wmma<<<ggrid, 256, SMEM_GEMM>>>(pxh, pxl, pWh + 2 * WSZ, pWl + 2 * WSZ, pV, 1);

    split_fp32<<<nx4 / 256, 256>>>(pQ, pQh, pQl, nx4);
    split_fp32<<<nx4 / 256, 256>>>(pK, pKh, pKl, nx4);
    split_fp32<<<nx4 / 256, 256>>>(pV, pVh, pVl, nx4);

    dim3 agrid(S_ / QROWS, B_ * NUM_HEADS);   // (16, 32)
    attn_mma<<<agrid, 256, SMEM_ATTN>>>(pQh, pQl, pKh, pKl, pVh, pVl, pAh, pAl);

    gemm_wmma<<<ggrid, 256, SMEM_GEMM>>>(pAh, pAl, pWh + 3 * WSZ, pWl + 3 * WSZ, out, 0);
}